// round 8
// baseline (speedup 1.0000x reference)
#include <cuda_runtime.h>
#include <cuda_fp16.h>
#include <cstdint>
#include <math.h>

// ---------------------------------------------------------------------------
// KANConv2d: expanded feature map (silu + 8 uniform cubic B-spline basis
// channels per input channel) -> single 3x3 conv as implicit GEMM (mma.sync).
// Single-pass fp16, fp32 accumulate. 128 CTAs x (M128,N128), 256 threads,
// 8 warps with 64x32 warp tiles (smem-read traffic 192B/MMA < tensor floor),
// 6-stage cp.async pipeline, one barrier per 128-K (paired chunks).
// ---------------------------------------------------------------------------

#define BATCH 4
#define CIN 64
#define OUTC 128
#define PH 66
#define PW 66
#define CF 576          // 64 ch * 9 feats
#define KTOT 5184       // 9 taps * 576
#define NCHUNK 81       // 5184 / 64
#define NSTAGE 6

// device scratch (allocation-free)
__device__ __align__(16) __half g_Ff[BATCH * PH * PW * CF];
__device__ __align__(16) __half g_Bf[OUTC * KTOT];

// ---------------------------------------------------------------------------
__device__ __forceinline__ uint32_t smem_u32(const void* p) {
    uint32_t a;
    asm("{ .reg .u64 t; cvta.to.shared.u64 t, %1; cvt.u32.u64 %0, t; }"
        : "=r"(a) : "l"(p));
    return a;
}

#define CP16(dst, src) \
    asm volatile("cp.async.cg.shared.global [%0], [%1], 16;" \
                 :: "r"(dst), "l"(src) : "memory")
#define CP_COMMIT() asm volatile("cp.async.commit_group;" ::: "memory")
#define CP_WAIT(n)  asm volatile("cp.async.wait_group %0;" :: "n"(n) : "memory")

#define LDSM4(r0, r1, r2, r3, a) \
    asm volatile("ldmatrix.sync.aligned.m8n8.x4.shared.b16 {%0,%1,%2,%3}, [%4];" \
                 : "=r"(r0), "=r"(r1), "=r"(r2), "=r"(r3) : "r"(a))

#define MMA16816(d, a, b0, b1) \
    asm volatile("mma.sync.aligned.m16n8k16.row.col.f32.f16.f16.f32 " \
                 "{%0,%1,%2,%3}, {%4,%5,%6,%7}, {%8,%9}, {%0,%1,%2,%3};" \
                 : "+f"((d)[0]), "+f"((d)[1]), "+f"((d)[2]), "+f"((d)[3]) \
                 : "r"((a)[0]), "r"((a)[1]), "r"((a)[2]), "r"((a)[3]), \
                   "r"(b0), "r"(b1))

// ---------------------------------------------------------------------------
// feature math: silu + 8 uniform cubic B-spline basis values (grid [-2.2,2.2])
// ---------------------------------------------------------------------------
__device__ __forceinline__ void feat9(float v, float* dst) {
    dst[0] = v / (1.0f + __expf(-v));
    float s = (v + 2.2f) * 2.5f;
    int j = (int)floorf(s);
    float B0 = 0.f, B1 = 0.f, B2 = 0.f, B3 = 0.f;
    if (j >= 0 && j <= 10) {
        float u  = (v - (0.4f * (float)j - 2.2f)) * 2.5f;
        float um = 1.0f - u;
        float u2 = u * u, u3 = u2 * u;
        B3 = u3 * (1.0f / 6.0f);
        B2 = (-3.0f * u3 + 3.0f * u2 + 3.0f * u + 1.0f) * (1.0f / 6.0f);
        B1 = (3.0f * u3 - 6.0f * u2 + 4.0f) * (1.0f / 6.0f);
        B0 = um * um * um * (1.0f / 6.0f);
    }
#pragma unroll
    for (int i = 0; i < 8; i++) {
        int rel = j - i;
        dst[1 + i] = (rel == 0) ? B3 : (rel == 1) ? B2 : (rel == 2) ? B1
                   : (rel == 3) ? B0 : 0.0f;
    }
}

// ---------------------------------------------------------------------------
// fused pre-kernel: blocks [0,512) feat interior, [512,576) border,
// [576,3168) weight fold. 256 threads.
// ---------------------------------------------------------------------------
__global__ __launch_bounds__(256) void pre_kernel(
    const float* __restrict__ x, const float* __restrict__ bw,
    const float* __restrict__ sw, const float* __restrict__ ss) {
    extern __shared__ char dynsm[];
    const int blk = blockIdx.x;
    const int tid = threadIdx.x;

    if (blk < 512) {
        // ---- feat: blk = b*128 + iy*2 + xhalf ----
        float* slab   = reinterpret_cast<float*>(dynsm);            // 8448 B
        uint32_t* stH = reinterpret_cast<uint32_t*>(dynsm + 8448);  // 36992 B
        const int b  = blk >> 7;
        const int iy = (blk >> 1) & 63;
        const int xb = (blk & 1) * 32;

        for (int i = tid; i < 64 * 32; i += 256) {
            int c = i >> 5, px = i & 31;
            slab[c * 33 + px] = x[(((b * 64 + c) * 64 + iy) << 6) + xb + px];
        }
        __syncthreads();

        const int px = tid >> 3;
        const int cg = tid & 7;
#pragma unroll
        for (int pair = 0; pair < 4; pair++) {
            int c0 = cg * 8 + pair * 2;
            float f[18];
            feat9(slab[c0 * 33 + px], f);
            feat9(slab[(c0 + 1) * 33 + px], f + 9);
            int wb = px * 289 + cg * 36 + pair * 9;
#pragma unroll
            for (int q = 0; q < 9; q++) {
                __half2 th = __halves2half2(__float2half_rn(f[2 * q]),
                                            __float2half_rn(f[2 * q + 1]));
                stH[wb + q] = *reinterpret_cast<uint32_t*>(&th);
            }
        }
        __syncthreads();

        const size_t pixbase = ((size_t)((b * PH + iy + 1) * PW + xb + 1)) * CF;
        uint32_t* dH = reinterpret_cast<uint32_t*>(g_Ff + pixbase);
        for (int i = tid; i < 32 * 288; i += 256) {
            int p = i / 288, w = i - p * 288;
            dH[i] = stH[p * 289 + w];
        }
    } else if (blk < 576) {
        // ---- border: padded border pixels get features of x = 0 ----
        float zf[9];
        feat9(0.0f, zf);
        __half zh[9];
#pragma unroll
        for (int q = 0; q < 9; q++) zh[q] = __float2half_rn(zf[q]);

        for (int i = blk - 512; i < 4 * 260; i += 64) {
            int b = i / 260, r = i - b * 260;
            int py, pxx;
            if (r < 66)        { py = 0;  pxx = r; }
            else if (r < 132)  { py = 65; pxx = r - 66; }
            else { int t = r - 132; py = 1 + (t >> 1); pxx = (t & 1) * 65; }
            __half* dH = g_Ff + ((size_t)((b * PH + py) * PW + pxx)) * CF;
            for (int e = tid; e < CF; e += 256)
                dH[e] = zh[e % 9];
        }
    } else {
        // ---- weight fold -> [o][kk], kk = tap*576 + c*9 + ck, d = c*9+tap --
        int idx = (blk - 576) * 256 + tid;
        if (idx >= OUTC * KTOT) return;
        int o   = idx / KTOT;
        int kk  = idx - o * KTOT;
        int tap = kk / 576;
        int r   = kk - tap * 576;
        int c   = r / 9;
        int ck  = r - c * 9;
        int d   = c * 9 + tap;
        float v = ck ? sw[(o * 576 + d) * 8 + (ck - 1)] * ss[o * 576 + d]
                     : bw[o * 576 + d];
        g_Bf[idx] = __float2half_rn(v);
    }
}

// ---------------------------------------------------------------------------
// GEMM: 128 CTAs, M=128 x N=128, K=5184, fp16 mma.sync.
// 256 threads (8 warps: 2m x 4n, warp 64x32). 6-stage pipeline,
// barrier per 128-K. Per stage (32KB): [A 16K][B 16K], 128B rows, swizzled.
// ---------------------------------------------------------------------------
#define STAGE_BYTES 32768
#define T_A 0
#define T_B 16384

__global__ __launch_bounds__(256, 1) void gemm_kernel(float* __restrict__ out) {
    extern __shared__ char dynsm[];
    uint32_t raw  = smem_u32(dynsm);
    uint32_t base = (raw + 1023u) & ~1023u;

    const int tid  = threadIdx.x;
    const int wid  = tid >> 5;
    const int lane = tid & 31;
    const int wm   = wid & 1;    // 0..1 -> m base 0,64
    const int wn   = wid >> 1;   // 0..3 -> n base 0,32,64,96
    const int mbase = blockIdx.x * 128;

    // ---- cp.async mapping: row = tid>>1 (0..127), seg = tid&1 (64B half)
    const int row = tid >> 1;
    const int seg = tid & 1;
    const int npix = mbase + row;
    const int pb = npix >> 12;
    const int oy = (npix >> 6) & 63;
    const int ox = npix & 63;
    const __half* ap = g_Ff + ((size_t)((pb * PH + oy) * PW + ox)) * CF;
    const __half* bp = g_Bf + (size_t)row * KTOT;
    const uint32_t rowterm = (uint32_t)row * 128;
    const uint32_t rowpat  = ((uint32_t)row & 7) << 4;

    auto load_chunk = [&](int kc, int stage) {
        int tap = kc / 9;
        int sub = kc - tap * 9;
        int kh = tap / 3, kw = tap - kh * 3;
        int aoff = (kh * PW + kw) * CF + sub * 64 + seg * 32;  // fp16 elements
        int boff = kc * 64 + seg * 32;
        const char* sA = (const char*)(ap + aoff);
        const char* sB = (const char*)(bp + boff);
        uint32_t sb = base + (uint32_t)stage * STAGE_BYTES + rowterm;
#pragma unroll
        for (int q = 0; q < 4; q++) {
            uint32_t kb = (uint32_t)(seg * 64 + q * 16);
            uint32_t d  = sb + (kb ^ rowpat);
            CP16(d + T_A, sA + q * 16);
            CP16(d + T_B, sB + q * 16);
        }
        CP_COMMIT();
    };

    // ---- ldmatrix lane addressing ----
    const int rA  = lane & 15;
    const uint32_t kA = ((uint32_t)(lane >> 4)) * 16;   // bytes
    uint32_t aRow[4], aPat[4];
#pragma unroll
    for (int mt = 0; mt < 4; mt++) {
        int rr = wm * 64 + mt * 16 + rA;
        aRow[mt] = (uint32_t)rr * 128;
        aPat[mt] = ((uint32_t)rr & 7) << 4;
    }
    const int rBl = (lane & 7) + ((lane >> 4) & 1) * 8;
    const uint32_t kB = ((uint32_t)((lane >> 3) & 1)) * 16;
    uint32_t bRow[2], bPat[2];
#pragma unroll
    for (int nt = 0; nt < 2; nt++) {
        int rr = wn * 32 + nt * 16 + rBl;
        bRow[nt] = (uint32_t)rr * 128;
        bPat[nt] = ((uint32_t)rr & 7) << 4;
    }

    float acc[4][4][4];
#pragma unroll
    for (int i = 0; i < 4; i++)
#pragma unroll
        for (int j = 0; j < 4; j++)
#pragma unroll
            for (int q = 0; q < 4; q++) acc[i][j][q] = 0.0f;

    auto compute_chunk = [&](uint32_t stg) {
        const uint32_t bb = base + stg * STAGE_BYTES;
#pragma unroll
        for (int kk = 0; kk < 4; kk++) {
            uint32_t af[4][4];
#pragma unroll
            for (int mt = 0; mt < 4; mt++) {
                uint32_t addr = bb + T_A + aRow[mt] + (((uint32_t)(kk * 32) + kA) ^ aPat[mt]);
                LDSM4(af[mt][0], af[mt][1], af[mt][2], af[mt][3], addr);
            }
#pragma unroll
            for (int nt = 0; nt < 2; nt++) {
                uint32_t addr = bb + T_B + bRow[nt] + (((uint32_t)(kk * 32) + kB) ^ bPat[nt]);
                uint32_t bf[4];
                LDSM4(bf[0], bf[1], bf[2], bf[3], addr);
#pragma unroll
                for (int mt = 0; mt < 4; mt++) {
#pragma unroll
                    for (int sub = 0; sub < 2; sub++) {
                        MMA16816(acc[mt][nt * 2 + sub], af[mt],
                                 bf[sub * 2], bf[sub * 2 + 1]);
                    }
                }
            }
        }
    };

    // prologue: chunks 0..3 into stages 0..3
#pragma unroll
    for (int s = 0; s < 4; s++) load_chunk(s, s);

    // mainloop: one barrier per chunk pair (128 K). s0 cycles 0,2,4.
    int s0 = 0;
    for (int it = 0; it < 41; it++) {
        const int c0 = it * 2;
        CP_WAIT(2);
        __syncthreads();

        const int ls0 = (s0 >= 2) ? s0 - 2 : s0 + 4;   // (s0+4) mod 6
        if (c0 + 4 < NCHUNK) load_chunk(c0 + 4, ls0); else CP_COMMIT();
        if (c0 + 5 < NCHUNK) load_chunk(c0 + 5, ls0 + 1); else CP_COMMIT();

        compute_chunk((uint32_t)s0);
        if (c0 + 1 < NCHUNK) compute_chunk((uint32_t)(s0 + 1));

        s0 += 2; if (s0 == 6) s0 = 0;
    }
    __syncthreads();

    // ---- epilogue: stage through smem (transpose), coalesced global write --
    float* st = reinterpret_cast<float*>(dynsm + (base - raw));
    const int g  = lane >> 2;
    const int tg = lane & 3;
#pragma unroll
    for (int mt = 0; mt < 4; mt++) {
#pragma unroll
        for (int n8 = 0; n8 < 4; n8++) {
            int m0 = wm * 64 + mt * 16 + g;
            int n0 = wn * 32 + n8 * 8 + tg * 2;
            const float* c = acc[mt][n8];
            st[m0 * 129 + n0]           = c[0];
            st[m0 * 129 + n0 + 1]       = c[1];
            st[(m0 + 8) * 129 + n0]     = c[2];
            st[(m0 + 8) * 129 + n0 + 1] = c[3];
        }
    }
    __syncthreads();

    const int b_ = mbase >> 12;
    const int spb = mbase & 4095;
#pragma unroll
    for (int r = 0; r < 64; r++) {
        int idx = r * 256 + tid;
        int o = idx >> 7;
        int m = idx & 127;
        out[(((size_t)(b_ * OUTC + o)) << 12) + spb + m] = st[m * 129 + o];
    }
}

// ---------------------------------------------------------------------------
extern "C" void kernel_launch(void* const* d_in, const int* in_sizes, int n_in,
                              void* d_out, int out_size) {
    const float* x  = (const float*)d_in[0];
    const float* bw = (const float*)d_in[1];
    const float* sw = (const float*)d_in[2];
    const float* ss = (const float*)d_in[3];
    float* out = (float*)d_out;

    cudaFuncSetAttribute(pre_kernel, cudaFuncAttributeMaxDynamicSharedMemorySize, 50176);
    cudaFuncSetAttribute(gemm_kernel, cudaFuncAttributeMaxDynamicSharedMemorySize, 197632);

    // blocks: 512 feat + 64 border + ceil(663552/256)=2592 weight
    pre_kernel<<<512 + 64 + 2592, 256, 45440>>>(x, bw, sw, ss);
    gemm_kernel<<<128, 256, 197632>>>(out);
}

// round 9
// speedup vs baseline: 1.0205x; 1.0205x over previous
#include <cuda_runtime.h>
#include <cuda_fp16.h>
#include <cstdint>
#include <math.h>

// ---------------------------------------------------------------------------
// KANConv2d: expanded feature map (silu + 8 uniform cubic B-spline basis
// channels per input channel) -> single 3x3 conv as implicit GEMM (mma.sync).
// Single-pass fp16, fp32 accumulate. 128 CTAs x (M128,N128), 256 threads,
// 8 warps with 64x32 warp tiles + EXPLICIT fragment double-buffering across
// an 8-kk window per barrier (paired 64-K chunks), 6-stage cp.async pipeline.
// ---------------------------------------------------------------------------

#define BATCH 4
#define CIN 64
#define OUTC 128
#define PH 66
#define PW 66
#define CF 576          // 64 ch * 9 feats
#define KTOT 5184       // 9 taps * 576
#define NCHUNK 81       // 5184 / 64
#define NSTAGE 6

// device scratch (allocation-free)
__device__ __align__(16) __half g_Ff[BATCH * PH * PW * CF];
__device__ __align__(16) __half g_Bf[OUTC * KTOT];

// ---------------------------------------------------------------------------
__device__ __forceinline__ uint32_t smem_u32(const void* p) {
    uint32_t a;
    asm("{ .reg .u64 t; cvta.to.shared.u64 t, %1; cvt.u32.u64 %0, t; }"
        : "=r"(a) : "l"(p));
    return a;
}

#define CP16(dst, src) \
    asm volatile("cp.async.cg.shared.global [%0], [%1], 16;" \
                 :: "r"(dst), "l"(src) : "memory")
#define CP_COMMIT() asm volatile("cp.async.commit_group;" ::: "memory")
#define CP_WAIT(n)  asm volatile("cp.async.wait_group %0;" :: "n"(n) : "memory")

#define LDSM4(r0, r1, r2, r3, a) \
    asm volatile("ldmatrix.sync.aligned.m8n8.x4.shared.b16 {%0,%1,%2,%3}, [%4];" \
                 : "=r"(r0), "=r"(r1), "=r"(r2), "=r"(r3) : "r"(a))

#define MMA16816(d, a, b0, b1) \
    asm volatile("mma.sync.aligned.m16n8k16.row.col.f32.f16.f16.f32 " \
                 "{%0,%1,%2,%3}, {%4,%5,%6,%7}, {%8,%9}, {%0,%1,%2,%3};" \
                 : "+f"((d)[0]), "+f"((d)[1]), "+f"((d)[2]), "+f"((d)[3]) \
                 : "r"((a)[0]), "r"((a)[1]), "r"((a)[2]), "r"((a)[3]), \
                   "r"(b0), "r"(b1))

// ---------------------------------------------------------------------------
// feature math: silu + 8 uniform cubic B-spline basis values (grid [-2.2,2.2])
// ---------------------------------------------------------------------------
__device__ __forceinline__ void feat9(float v, float* dst) {
    dst[0] = v / (1.0f + __expf(-v));
    float s = (v + 2.2f) * 2.5f;
    int j = (int)floorf(s);
    float B0 = 0.f, B1 = 0.f, B2 = 0.f, B3 = 0.f;
    if (j >= 0 && j <= 10) {
        float u  = (v - (0.4f * (float)j - 2.2f)) * 2.5f;
        float um = 1.0f - u;
        float u2 = u * u, u3 = u2 * u;
        B3 = u3 * (1.0f / 6.0f);
        B2 = (-3.0f * u3 + 3.0f * u2 + 3.0f * u + 1.0f) * (1.0f / 6.0f);
        B1 = (3.0f * u3 - 6.0f * u2 + 4.0f) * (1.0f / 6.0f);
        B0 = um * um * um * (1.0f / 6.0f);
    }
#pragma unroll
    for (int i = 0; i < 8; i++) {
        int rel = j - i;
        dst[1 + i] = (rel == 0) ? B3 : (rel == 1) ? B2 : (rel == 2) ? B1
                   : (rel == 3) ? B0 : 0.0f;
    }
}

// ---------------------------------------------------------------------------
// fused pre-kernel: blocks [0,512) feat interior, [512,576) border,
// [576,3168) weight fold. 256 threads.
// ---------------------------------------------------------------------------
__global__ __launch_bounds__(256) void pre_kernel(
    const float* __restrict__ x, const float* __restrict__ bw,
    const float* __restrict__ sw, const float* __restrict__ ss) {
    extern __shared__ char dynsm[];
    const int blk = blockIdx.x;
    const int tid = threadIdx.x;

    if (blk < 512) {
        // ---- feat: blk = b*128 + iy*2 + xhalf ----
        float* slab   = reinterpret_cast<float*>(dynsm);            // 8448 B
        uint32_t* stH = reinterpret_cast<uint32_t*>(dynsm + 8448);  // 36992 B
        const int b  = blk >> 7;
        const int iy = (blk >> 1) & 63;
        const int xb = (blk & 1) * 32;

        for (int i = tid; i < 64 * 32; i += 256) {
            int c = i >> 5, px = i & 31;
            slab[c * 33 + px] = x[(((b * 64 + c) * 64 + iy) << 6) + xb + px];
        }
        __syncthreads();

        const int px = tid >> 3;
        const int cg = tid & 7;
#pragma unroll
        for (int pair = 0; pair < 4; pair++) {
            int c0 = cg * 8 + pair * 2;
            float f[18];
            feat9(slab[c0 * 33 + px], f);
            feat9(slab[(c0 + 1) * 33 + px], f + 9);
            int wb = px * 289 + cg * 36 + pair * 9;
#pragma unroll
            for (int q = 0; q < 9; q++) {
                __half2 th = __halves2half2(__float2half_rn(f[2 * q]),
                                            __float2half_rn(f[2 * q + 1]));
                stH[wb + q] = *reinterpret_cast<uint32_t*>(&th);
            }
        }
        __syncthreads();

        const size_t pixbase = ((size_t)((b * PH + iy + 1) * PW + xb + 1)) * CF;
        uint32_t* dH = reinterpret_cast<uint32_t*>(g_Ff + pixbase);
        for (int i = tid; i < 32 * 288; i += 256) {
            int p = i / 288, w = i - p * 288;
            dH[i] = stH[p * 289 + w];
        }
    } else if (blk < 576) {
        // ---- border: padded border pixels get features of x = 0 ----
        float zf[9];
        feat9(0.0f, zf);
        __half zh[9];
#pragma unroll
        for (int q = 0; q < 9; q++) zh[q] = __float2half_rn(zf[q]);

        for (int i = blk - 512; i < 4 * 260; i += 64) {
            int b = i / 260, r = i - b * 260;
            int py, pxx;
            if (r < 66)        { py = 0;  pxx = r; }
            else if (r < 132)  { py = 65; pxx = r - 66; }
            else { int t = r - 132; py = 1 + (t >> 1); pxx = (t & 1) * 65; }
            __half* dH = g_Ff + ((size_t)((b * PH + py) * PW + pxx)) * CF;
            for (int e = tid; e < CF; e += 256)
                dH[e] = zh[e % 9];
        }
    } else {
        // ---- weight fold -> [o][kk], kk = tap*576 + c*9 + ck, d = c*9+tap --
        int idx = (blk - 576) * 256 + tid;
        if (idx >= OUTC * KTOT) return;
        int o   = idx / KTOT;
        int kk  = idx - o * KTOT;
        int tap = kk / 576;
        int r   = kk - tap * 576;
        int c   = r / 9;
        int ck  = r - c * 9;
        int d   = c * 9 + tap;
        float v = ck ? sw[(o * 576 + d) * 8 + (ck - 1)] * ss[o * 576 + d]
                     : bw[o * 576 + d];
        g_Bf[idx] = __float2half_rn(v);
    }
}

// ---------------------------------------------------------------------------
// GEMM: 128 CTAs, M=128 x N=128, K=5184, fp16 mma.sync.
// 256 threads (8 warps: 2m x 4n, warp 64x32). 6-stage pipeline, barrier per
// 128-K, 8-kk fragment-double-buffered compute window.
// Per stage (32KB): [A 16K][B 16K], 128B rows, swizzled.
// ---------------------------------------------------------------------------
#define STAGE_BYTES 32768
#define T_A 0
#define T_B 16384

__global__ __launch_bounds__(256, 1) void gemm_kernel(float* __restrict__ out) {
    extern __shared__ char dynsm[];
    uint32_t raw  = smem_u32(dynsm);
    uint32_t base = (raw + 1023u) & ~1023u;

    const int tid  = threadIdx.x;
    const int wid  = tid >> 5;
    const int lane = tid & 31;
    const int wm   = wid & 1;    // 0..1 -> m base 0,64
    const int wn   = wid >> 1;   // 0..3 -> n base 0,32,64,96
    const int mbase = blockIdx.x * 128;

    // ---- cp.async mapping: row = tid>>1 (0..127), seg = tid&1 (64B half)
    const int row = tid >> 1;
    const int seg = tid & 1;
    const int npix = mbase + row;
    const int pb = npix >> 12;
    const int oy = (npix >> 6) & 63;
    const int ox = npix & 63;
    const __half* ap = g_Ff + ((size_t)((pb * PH + oy) * PW + ox)) * CF;
    const __half* bp = g_Bf + (size_t)row * KTOT;
    const uint32_t rowterm = (uint32_t)row * 128;
    const uint32_t rowpat  = ((uint32_t)row & 7) << 4;

    auto load_chunk = [&](int kc, int stage) {
        int tap = kc / 9;
        int sub = kc - tap * 9;
        int kh = tap / 3, kw = tap - kh * 3;
        int aoff = (kh * PW + kw) * CF + sub * 64 + seg * 32;  // fp16 elements
        int boff = kc * 64 + seg * 32;
        const char* sA = (const char*)(ap + aoff);
        const char* sB = (const char*)(bp + boff);
        uint32_t sb = base + (uint32_t)stage * STAGE_BYTES + rowterm;
#pragma unroll
        for (int q = 0; q < 4; q++) {
            uint32_t kb = (uint32_t)(seg * 64 + q * 16);
            uint32_t d  = sb + (kb ^ rowpat);
            CP16(d + T_A, sA + q * 16);
            CP16(d + T_B, sB + q * 16);
        }
        CP_COMMIT();
    };

    // ---- ldmatrix lane addressing ----
    const int rA  = lane & 15;
    const uint32_t kA = ((uint32_t)(lane >> 4)) * 16;   // bytes
    uint32_t aRow[4], aPat[4];
#pragma unroll
    for (int mt = 0; mt < 4; mt++) {
        int rr = wm * 64 + mt * 16 + rA;
        aRow[mt] = (uint32_t)rr * 128;
        aPat[mt] = ((uint32_t)rr & 7) << 4;
    }
    const int rBl = (lane & 7) + ((lane >> 4) & 1) * 8;
    const uint32_t kB = ((uint32_t)((lane >> 3) & 1)) * 16;
    uint32_t bRow[2], bPat[2];
#pragma unroll
    for (int nt = 0; nt < 2; nt++) {
        int rr = wn * 32 + nt * 16 + rBl;
        bRow[nt] = (uint32_t)rr * 128;
        bPat[nt] = ((uint32_t)rr & 7) << 4;
    }

    float acc[4][4][4];
#pragma unroll
    for (int i = 0; i < 4; i++)
#pragma unroll
        for (int j = 0; j < 4; j++)
#pragma unroll
            for (int q = 0; q < 4; q++) acc[i][j][q] = 0.0f;

    // fragment load: 4 A-LDSM4 + 2 B-LDSM4 for one 16-K slice
    auto ldfrag = [&](uint32_t bb, int kk, uint32_t (&af)[4][4],
                      uint32_t (&bf)[2][4]) {
        const uint32_t kbyte = (uint32_t)(kk * 32);
#pragma unroll
        for (int mt = 0; mt < 4; mt++) {
            uint32_t addr = bb + T_A + aRow[mt] + ((kbyte + kA) ^ aPat[mt]);
            LDSM4(af[mt][0], af[mt][1], af[mt][2], af[mt][3], addr);
        }
#pragma unroll
        for (int nt = 0; nt < 2; nt++) {
            uint32_t addr = bb + T_B + bRow[nt] + ((kbyte + kB) ^ bPat[nt]);
            LDSM4(bf[nt][0], bf[nt][1], bf[nt][2], bf[nt][3], addr);
        }
    };

    auto domma = [&](uint32_t (&af)[4][4], uint32_t (&bf)[2][4]) {
#pragma unroll
        for (int nt = 0; nt < 2; nt++)
#pragma unroll
            for (int mt = 0; mt < 4; mt++)
#pragma unroll
                for (int sub = 0; sub < 2; sub++)
                    MMA16816(acc[mt][nt * 2 + sub], af[mt],
                             bf[nt][sub * 2], bf[nt][sub * 2 + 1]);
    };

    uint32_t af[2][4][4], bf[2][2][4];

    // compute two consecutive 64-K chunks (stages sA, sB) as one 8-kk window
    auto compute_pair = [&](int sA, int sB) {
        const uint32_t bbA = base + (uint32_t)sA * STAGE_BYTES;
        const uint32_t bbB = base + (uint32_t)sB * STAGE_BYTES;
        ldfrag(bbA, 0, af[0], bf[0]);
#pragma unroll
        for (int kk = 0; kk < 8; kk++) {
            const int cur = kk & 1;
            if (kk < 7) {
                const uint32_t bb = (kk + 1 < 4) ? bbA : bbB;
                ldfrag(bb, (kk + 1) & 3, af[cur ^ 1], bf[cur ^ 1]);
            }
            domma(af[cur], bf[cur]);
        }
    };

    auto compute_single = [&](int sA) {
        const uint32_t bbA = base + (uint32_t)sA * STAGE_BYTES;
        ldfrag(bbA, 0, af[0], bf[0]);
#pragma unroll
        for (int kk = 0; kk < 4; kk++) {
            const int cur = kk & 1;
            if (kk < 3) ldfrag(bbA, kk + 1, af[cur ^ 1], bf[cur ^ 1]);
            domma(af[cur], bf[cur]);
        }
    };

    // prologue: chunks 0..3 into stages 0..3
#pragma unroll
    for (int s = 0; s < 4; s++) load_chunk(s, s);

    // mainloop: 40 iterations x 2 chunks; chunk c lives in stage c % 6
    int s0 = 0;
    for (int it = 0; it < 40; it++) {
        const int c0 = it * 2;
        CP_WAIT(2);
        __syncthreads();

        const int ls0 = (s0 >= 2) ? s0 - 2 : s0 + 4;   // (s0+4) mod 6
        if (c0 + 4 < NCHUNK) load_chunk(c0 + 4, ls0); else CP_COMMIT();
        if (c0 + 5 < NCHUNK) load_chunk(c0 + 5, (ls0 + 1 == 6) ? 0 : ls0 + 1);
        else CP_COMMIT();

        compute_pair(s0, s0 + 1);

        s0 += 2; if (s0 == 6) s0 = 0;
    }
    // final chunk 80 (stage 80 % 6 == 2 == s0 here)
    CP_WAIT(0);
    __syncthreads();
    compute_single(s0);
    __syncthreads();

    // ---- epilogue: stage through smem (transpose), coalesced global write --
    float* st = reinterpret_cast<float*>(dynsm + (base - raw));
    const int g  = lane >> 2;
    const int tg = lane & 3;
#pragma unroll
    for (int mt = 0; mt < 4; mt++) {
#pragma unroll
        for (int n8 = 0; n8 < 4; n8++) {
            int m0 = wm * 64 + mt * 16 + g;
            int n0 = wn * 32 + n8 * 8 + tg * 2;
            const float* c = acc[mt][n8];
            st[m0 * 129 + n0]           = c[0];
            st[m0 * 129 + n0 + 1]       = c[1];
            st[(m0 + 8) * 129 + n0]     = c[2];
            st[(m0 + 8) * 129 + n0 + 1] = c[3];
        }
    }
    __syncthreads();

    const int b_ = mbase >> 12;
    const int spb = mbase & 4095;
#pragma unroll
    for (int r = 0; r < 64; r++) {
        int idx = r * 256 + tid;
        int o = idx >> 7;
        int m = idx & 127;
        out[(((size_t)(b_ * OUTC + o)) << 12) + spb + m] = st[m * 129 + o];
    }
}

// ---------------------------------------------------------------------------
extern "C" void kernel_launch(void* const* d_in, const int* in_sizes, int n_in,
                              void* d_out, int out_size) {
    const float* x  = (const float*)d_in[0];
    const float* bw = (const float*)d_in[1];
    const float* sw = (const float*)d_in[2];
    const float* ss = (const float*)d_in[3];
    float* out = (float*)d_out;

    cudaFuncSetAttribute(pre_kernel, cudaFuncAttributeMaxDynamicSharedMemorySize, 50176);
    cudaFuncSetAttribute(gemm_kernel, cudaFuncAttributeMaxDynamicSharedMemorySize, 197632);

    // blocks: 512 feat + 64 border + ceil(663552/256)=2592 weight
    pre_kernel<<<512 + 64 + 2592, 256, 45440>>>(x, bw, sw, ss);
    gemm_kernel<<<128, 256, 197632>>>(out);
}

// round 10
// speedup vs baseline: 1.1388x; 1.1160x over previous
#include <cuda_runtime.h>
#include <cuda_fp16.h>
#include <cstdint>
#include <math.h>

// ---------------------------------------------------------------------------
// KANConv2d: expanded feature map (silu + 8 uniform cubic B-spline basis
// channels per input channel) -> single 3x3 conv as implicit GEMM (mma.sync).
// Single-pass fp16, fp32 accumulate. 128 CTAs x (M128,N128), 512 threads,
// 16 warps x (32x32) tiles, per-warp fragment double-buffering (LDSM of kk+1
// overlaps MMA of kk), 6-stage cp.async pipeline, barrier per 128-K.
// ---------------------------------------------------------------------------

#define BATCH 4
#define CIN 64
#define OUTC 128
#define PH 66
#define PW 66
#define CF 576          // 64 ch * 9 feats
#define KTOT 5184       // 9 taps * 576
#define NCHUNK 81       // 5184 / 64
#define NSTAGE 6

// device scratch (allocation-free)
__device__ __align__(16) __half g_Ff[BATCH * PH * PW * CF];
__device__ __align__(16) __half g_Bf[OUTC * KTOT];

// ---------------------------------------------------------------------------
__device__ __forceinline__ uint32_t smem_u32(const void* p) {
    uint32_t a;
    asm("{ .reg .u64 t; cvta.to.shared.u64 t, %1; cvt.u32.u64 %0, t; }"
        : "=r"(a) : "l"(p));
    return a;
}

#define CP16(dst, src) \
    asm volatile("cp.async.cg.shared.global [%0], [%1], 16;" \
                 :: "r"(dst), "l"(src) : "memory")
#define CP_COMMIT() asm volatile("cp.async.commit_group;" ::: "memory")
#define CP_WAIT(n)  asm volatile("cp.async.wait_group %0;" :: "n"(n) : "memory")

#define LDSM4(r0, r1, r2, r3, a) \
    asm volatile("ldmatrix.sync.aligned.m8n8.x4.shared.b16 {%0,%1,%2,%3}, [%4];" \
                 : "=r"(r0), "=r"(r1), "=r"(r2), "=r"(r3) : "r"(a))

#define MMA16816(d, a, b0, b1) \
    asm volatile("mma.sync.aligned.m16n8k16.row.col.f32.f16.f16.f32 " \
                 "{%0,%1,%2,%3}, {%4,%5,%6,%7}, {%8,%9}, {%0,%1,%2,%3};" \
                 : "+f"((d)[0]), "+f"((d)[1]), "+f"((d)[2]), "+f"((d)[3]) \
                 : "r"((a)[0]), "r"((a)[1]), "r"((a)[2]), "r"((a)[3]), \
                   "r"(b0), "r"(b1))

// ---------------------------------------------------------------------------
// feature math: silu + 8 uniform cubic B-spline basis values (grid [-2.2,2.2])
// ---------------------------------------------------------------------------
__device__ __forceinline__ void feat9(float v, float* dst) {
    dst[0] = v / (1.0f + __expf(-v));
    float s = (v + 2.2f) * 2.5f;
    int j = (int)floorf(s);
    float B0 = 0.f, B1 = 0.f, B2 = 0.f, B3 = 0.f;
    if (j >= 0 && j <= 10) {
        float u  = (v - (0.4f * (float)j - 2.2f)) * 2.5f;
        float um = 1.0f - u;
        float u2 = u * u, u3 = u2 * u;
        B3 = u3 * (1.0f / 6.0f);
        B2 = (-3.0f * u3 + 3.0f * u2 + 3.0f * u + 1.0f) * (1.0f / 6.0f);
        B1 = (3.0f * u3 - 6.0f * u2 + 4.0f) * (1.0f / 6.0f);
        B0 = um * um * um * (1.0f / 6.0f);
    }
#pragma unroll
    for (int i = 0; i < 8; i++) {
        int rel = j - i;
        dst[1 + i] = (rel == 0) ? B3 : (rel == 1) ? B2 : (rel == 2) ? B1
                   : (rel == 3) ? B0 : 0.0f;
    }
}

// ---------------------------------------------------------------------------
// fused pre-kernel: blocks [0,512) feat interior, [512,576) border,
// [576,3168) weight fold. 256 threads.
// ---------------------------------------------------------------------------
__global__ __launch_bounds__(256) void pre_kernel(
    const float* __restrict__ x, const float* __restrict__ bw,
    const float* __restrict__ sw, const float* __restrict__ ss) {
    extern __shared__ char dynsm[];
    const int blk = blockIdx.x;
    const int tid = threadIdx.x;

    if (blk < 512) {
        // ---- feat: blk = b*128 + iy*2 + xhalf ----
        float* slab   = reinterpret_cast<float*>(dynsm);            // 8448 B
        uint32_t* stH = reinterpret_cast<uint32_t*>(dynsm + 8448);  // 36992 B
        const int b  = blk >> 7;
        const int iy = (blk >> 1) & 63;
        const int xb = (blk & 1) * 32;

        for (int i = tid; i < 64 * 32; i += 256) {
            int c = i >> 5, px = i & 31;
            slab[c * 33 + px] = x[(((b * 64 + c) * 64 + iy) << 6) + xb + px];
        }
        __syncthreads();

        const int px = tid >> 3;
        const int cg = tid & 7;
#pragma unroll
        for (int pair = 0; pair < 4; pair++) {
            int c0 = cg * 8 + pair * 2;
            float f[18];
            feat9(slab[c0 * 33 + px], f);
            feat9(slab[(c0 + 1) * 33 + px], f + 9);
            int wb = px * 289 + cg * 36 + pair * 9;
#pragma unroll
            for (int q = 0; q < 9; q++) {
                __half2 th = __halves2half2(__float2half_rn(f[2 * q]),
                                            __float2half_rn(f[2 * q + 1]));
                stH[wb + q] = *reinterpret_cast<uint32_t*>(&th);
            }
        }
        __syncthreads();

        const size_t pixbase = ((size_t)((b * PH + iy + 1) * PW + xb + 1)) * CF;
        uint32_t* dH = reinterpret_cast<uint32_t*>(g_Ff + pixbase);
        for (int i = tid; i < 32 * 288; i += 256) {
            int p = i / 288, w = i - p * 288;
            dH[i] = stH[p * 289 + w];
        }
    } else if (blk < 576) {
        // ---- border: padded border pixels get features of x = 0 ----
        float zf[9];
        feat9(0.0f, zf);
        __half zh[9];
#pragma unroll
        for (int q = 0; q < 9; q++) zh[q] = __float2half_rn(zf[q]);

        for (int i = blk - 512; i < 4 * 260; i += 64) {
            int b = i / 260, r = i - b * 260;
            int py, pxx;
            if (r < 66)        { py = 0;  pxx = r; }
            else if (r < 132)  { py = 65; pxx = r - 66; }
            else { int t = r - 132; py = 1 + (t >> 1); pxx = (t & 1) * 65; }
            __half* dH = g_Ff + ((size_t)((b * PH + py) * PW + pxx)) * CF;
            for (int e = tid; e < CF; e += 256)
                dH[e] = zh[e % 9];
        }
    } else {
        // ---- weight fold -> [o][kk], kk = tap*576 + c*9 + ck, d = c*9+tap --
        int idx = (blk - 576) * 256 + tid;
        if (idx >= OUTC * KTOT) return;
        int o   = idx / KTOT;
        int kk  = idx - o * KTOT;
        int tap = kk / 576;
        int r   = kk - tap * 576;
        int c   = r / 9;
        int ck  = r - c * 9;
        int d   = c * 9 + tap;
        float v = ck ? sw[(o * 576 + d) * 8 + (ck - 1)] * ss[o * 576 + d]
                     : bw[o * 576 + d];
        g_Bf[idx] = __float2half_rn(v);
    }
}

// ---------------------------------------------------------------------------
// GEMM: 128 CTAs, M=128 x N=128, K=5184, fp16 mma.sync.
// 512 threads (16 warps 4x4, warp 32x32). 6-stage pipeline, barrier per
// 128-K, 8-kk fragment-double-buffered window. Stage (32KB): [A 16K][B 16K].
// ---------------------------------------------------------------------------
#define STAGE_BYTES 32768
#define T_A 0
#define T_B 16384

__global__ __launch_bounds__(512, 1) void gemm_kernel(float* __restrict__ out) {
    extern __shared__ char dynsm[];
    uint32_t raw  = smem_u32(dynsm);
    uint32_t base = (raw + 1023u) & ~1023u;

    const int tid  = threadIdx.x;
    const int wid  = tid >> 5;
    const int lane = tid & 31;
    const int wm   = wid & 3;
    const int wn   = wid >> 2;
    const int mbase = blockIdx.x * 128;

    // ---- cp.async mapping: row = tid>>2 (0..127), seg = tid&3 (32B quarter)
    const int row = tid >> 2;
    const int seg = tid & 3;
    const int npix = mbase + row;
    const int pb = npix >> 12;
    const int oy = (npix >> 6) & 63;
    const int ox = npix & 63;
    const __half* ap = g_Ff + ((size_t)((pb * PH + oy) * PW + ox)) * CF;
    const __half* bp = g_Bf + (size_t)row * KTOT;
    const uint32_t rowterm = (uint32_t)row * 128;
    const uint32_t rowpat  = ((uint32_t)row & 7) << 4;

    auto load_chunk = [&](int kc, int stage) {
        int tap = kc / 9;
        int sub = kc - tap * 9;
        int kh = tap / 3, kw = tap - kh * 3;
        int aoff = (kh * PW + kw) * CF + sub * 64 + seg * 16;  // fp16 elements
        int boff = kc * 64 + seg * 16;
        const char* sA = (const char*)(ap + aoff);
        const char* sB = (const char*)(bp + boff);
        uint32_t sb = base + (uint32_t)stage * STAGE_BYTES + rowterm;
#pragma unroll
        for (int q = 0; q < 2; q++) {
            uint32_t kb = (uint32_t)(seg * 32 + q * 16);
            uint32_t d  = sb + (kb ^ rowpat);
            CP16(d + T_A, sA + q * 16);
            CP16(d + T_B, sB + q * 16);
        }
        CP_COMMIT();
    };

    // ---- ldmatrix lane addressing ----
    const int rA  = lane & 15;
    const uint32_t kA = ((uint32_t)(lane >> 4)) * 16;   // bytes
    uint32_t aRow[2], aPat[2];
#pragma unroll
    for (int mt = 0; mt < 2; mt++) {
        int rr = wm * 32 + mt * 16 + rA;
        aRow[mt] = (uint32_t)rr * 128;
        aPat[mt] = ((uint32_t)rr & 7) << 4;
    }
    const int rBl = (lane & 7) + ((lane >> 4) & 1) * 8;
    const uint32_t kB = ((uint32_t)((lane >> 3) & 1)) * 16;
    uint32_t bRow[2], bPat[2];
#pragma unroll
    for (int nt = 0; nt < 2; nt++) {
        int rr = wn * 32 + nt * 16 + rBl;
        bRow[nt] = (uint32_t)rr * 128;
        bPat[nt] = ((uint32_t)rr & 7) << 4;
    }

    float acc[2][4][4];
#pragma unroll
    for (int i = 0; i < 2; i++)
#pragma unroll
        for (int j = 0; j < 4; j++)
#pragma unroll
            for (int q = 0; q < 4; q++) acc[i][j][q] = 0.0f;

    // fragment load: 2 A-LDSM4 + 2 B-LDSM4 for one 16-K slice of 32x32 tile
    auto ldfrag = [&](uint32_t bb, int kk, uint32_t (&af)[2][4],
                      uint32_t (&bf)[2][4]) {
        const uint32_t kbyte = (uint32_t)(kk * 32);
#pragma unroll
        for (int mt = 0; mt < 2; mt++) {
            uint32_t addr = bb + T_A + aRow[mt] + ((kbyte + kA) ^ aPat[mt]);
            LDSM4(af[mt][0], af[mt][1], af[mt][2], af[mt][3], addr);
        }
#pragma unroll
        for (int nt = 0; nt < 2; nt++) {
            uint32_t addr = bb + T_B + bRow[nt] + ((kbyte + kB) ^ bPat[nt]);
            LDSM4(bf[nt][0], bf[nt][1], bf[nt][2], bf[nt][3], addr);
        }
    };

    auto domma = [&](uint32_t (&af)[2][4], uint32_t (&bf)[2][4]) {
#pragma unroll
        for (int nt = 0; nt < 2; nt++)
#pragma unroll
            for (int mt = 0; mt < 2; mt++)
#pragma unroll
                for (int sub = 0; sub < 2; sub++)
                    MMA16816(acc[mt][nt * 2 + sub], af[mt],
                             bf[nt][sub * 2], bf[nt][sub * 2 + 1]);
    };

    uint32_t af[2][2][4], bf[2][2][4];

    // compute two consecutive 64-K chunks (stages sA, sB) as one 8-kk window
    auto compute_pair = [&](int sA, int sB) {
        const uint32_t bbA = base + (uint32_t)sA * STAGE_BYTES;
        const uint32_t bbB = base + (uint32_t)sB * STAGE_BYTES;
        ldfrag(bbA, 0, af[0], bf[0]);
#pragma unroll
        for (int kk = 0; kk < 8; kk++) {
            const int cur = kk & 1;
            if (kk < 7) {
                const uint32_t bb = (kk + 1 < 4) ? bbA : bbB;
                ldfrag(bb, (kk + 1) & 3, af[cur ^ 1], bf[cur ^ 1]);
            }
            domma(af[cur], bf[cur]);
        }
    };

    auto compute_single = [&](int sA) {
        const uint32_t bbA = base + (uint32_t)sA * STAGE_BYTES;
        ldfrag(bbA, 0, af[0], bf[0]);
#pragma unroll
        for (int kk = 0; kk < 4; kk++) {
            const int cur = kk & 1;
            if (kk < 3) ldfrag(bbA, kk + 1, af[cur ^ 1], bf[cur ^ 1]);
            domma(af[cur], bf[cur]);
        }
    };

    // prologue: chunks 0..3 into stages 0..3
#pragma unroll
    for (int s = 0; s < 4; s++) load_chunk(s, s);

    // mainloop: 40 iterations x 2 chunks; chunk c lives in stage c % 6
    int s0 = 0;
    for (int it = 0; it < 40; it++) {
        const int c0 = it * 2;
        CP_WAIT(2);
        __syncthreads();

        const int ls0 = (s0 >= 2) ? s0 - 2 : s0 + 4;   // (s0+4) mod 6
        load_chunk(c0 + 4, ls0);
        load_chunk(c0 + 5, (ls0 + 1 == 6) ? 0 : ls0 + 1);

        compute_pair(s0, s0 + 1);

        s0 += 2; if (s0 == 6) s0 = 0;
    }
    // final chunk 80 (stage 80 % 6 == 2 == s0 here)
    CP_WAIT(0);
    __syncthreads();
    compute_single(s0);
    __syncthreads();

    // ---- epilogue: stage through smem (transpose), coalesced global write --
    float* st = reinterpret_cast<float*>(dynsm + (base - raw));
    const int g  = lane >> 2;
    const int tg = lane & 3;
#pragma unroll
    for (int mt = 0; mt < 2; mt++) {
#pragma unroll
        for (int n8 = 0; n8 < 4; n8++) {
            int m0 = wm * 32 + mt * 16 + g;
            int n0 = wn * 32 + n8 * 8 + tg * 2;
            const float* c = acc[mt][n8];
            st[m0 * 129 + n0]           = c[0];
            st[m0 * 129 + n0 + 1]       = c[1];
            st[(m0 + 8) * 129 + n0]     = c[2];
            st[(m0 + 8) * 129 + n0 + 1] = c[3];
        }
    }
    __syncthreads();

    const int b_ = mbase >> 12;
    const int spb = mbase & 4095;
#pragma unroll
    for (int r = 0; r < 32; r++) {
        int idx = r * 512 + tid;
        int o = idx >> 7;
        int m = idx & 127;
        out[(((size_t)(b_ * OUTC + o)) << 12) + spb + m] = st[m * 129 + o];
    }
}

// ---------------------------------------------------------------------------
extern "C" void kernel_launch(void* const* d_in, const int* in_sizes, int n_in,
                              void* d_out, int out_size) {
    const float* x  = (const float*)d_in[0];
    const float* bw = (const float*)d_in[1];
    const float* sw = (const float*)d_in[2];
    const float* ss = (const float*)d_in[3];
    float* out = (float*)d_out;

    cudaFuncSetAttribute(pre_kernel, cudaFuncAttributeMaxDynamicSharedMemorySize, 50176);
    cudaFuncSetAttribute(gemm_kernel, cudaFuncAttributeMaxDynamicSharedMemorySize, 197632);

    // blocks: 512 feat + 64 border + ceil(663552/256)=2592 weight
    pre_kernel<<<512 + 64 + 2592, 256, 45440>>>(x, bw, sw, ss);
    gemm_kernel<<<128, 512, 197632>>>(out);
}

// round 11
// speedup vs baseline: 1.1615x; 1.0199x over previous
#include <cuda_runtime.h>
#include <cuda_fp16.h>
#include <cstdint>
#include <math.h>

// ---------------------------------------------------------------------------
// KANConv2d: expanded feature map (silu + 8 uniform cubic B-spline basis
// channels per input channel) -> single 3x3 conv as implicit GEMM (mma.sync).
// Single-pass fp16, fp32 accumulate. 128 CTAs x (M128,N128), 512 threads.
// 16 warps: 8 output tiles of 64x32, 2 warps per tile (K-split pair) ->
// 98KB LDSM traffic per 64-K chunk (vs 131KB at 32x32) with full 16-warp TLP.
// 6-stage cp.async pipeline, one barrier per 128-K (paired chunks).
// ---------------------------------------------------------------------------

#define BATCH 4
#define CIN 64
#define OUTC 128
#define PH 66
#define PW 66
#define CF 576          // 64 ch * 9 feats
#define KTOT 5184       // 9 taps * 576
#define NCHUNK 81       // 5184 / 64
#define NSTAGE 6

// device scratch (allocation-free)
__device__ __align__(16) __half g_Ff[BATCH * PH * PW * CF];
__device__ __align__(16) __half g_Bf[OUTC * KTOT];

// ---------------------------------------------------------------------------
__device__ __forceinline__ uint32_t smem_u32(const void* p) {
    uint32_t a;
    asm("{ .reg .u64 t; cvta.to.shared.u64 t, %1; cvt.u32.u64 %0, t; }"
        : "=r"(a) : "l"(p));
    return a;
}

#define CP16(dst, src) \
    asm volatile("cp.async.cg.shared.global [%0], [%1], 16;" \
                 :: "r"(dst), "l"(src) : "memory")
#define CP_COMMIT() asm volatile("cp.async.commit_group;" ::: "memory")
#define CP_WAIT(n)  asm volatile("cp.async.wait_group %0;" :: "n"(n) : "memory")

#define LDSM4(r0, r1, r2, r3, a) \
    asm volatile("ldmatrix.sync.aligned.m8n8.x4.shared.b16 {%0,%1,%2,%3}, [%4];" \
                 : "=r"(r0), "=r"(r1), "=r"(r2), "=r"(r3) : "r"(a))

#define MMA16816(d, a, b0, b1) \
    asm volatile("mma.sync.aligned.m16n8k16.row.col.f32.f16.f16.f32 " \
                 "{%0,%1,%2,%3}, {%4,%5,%6,%7}, {%8,%9}, {%0,%1,%2,%3};" \
                 : "+f"((d)[0]), "+f"((d)[1]), "+f"((d)[2]), "+f"((d)[3]) \
                 : "r"((a)[0]), "r"((a)[1]), "r"((a)[2]), "r"((a)[3]), \
                   "r"(b0), "r"(b1))

// ---------------------------------------------------------------------------
// feature math: silu + 8 uniform cubic B-spline basis values (grid [-2.2,2.2])
// ---------------------------------------------------------------------------
__device__ __forceinline__ void feat9(float v, float* dst) {
    dst[0] = v / (1.0f + __expf(-v));
    float s = (v + 2.2f) * 2.5f;
    int j = (int)floorf(s);
    float B0 = 0.f, B1 = 0.f, B2 = 0.f, B3 = 0.f;
    if (j >= 0 && j <= 10) {
        float u  = (v - (0.4f * (float)j - 2.2f)) * 2.5f;
        float um = 1.0f - u;
        float u2 = u * u, u3 = u2 * u;
        B3 = u3 * (1.0f / 6.0f);
        B2 = (-3.0f * u3 + 3.0f * u2 + 3.0f * u + 1.0f) * (1.0f / 6.0f);
        B1 = (3.0f * u3 - 6.0f * u2 + 4.0f) * (1.0f / 6.0f);
        B0 = um * um * um * (1.0f / 6.0f);
    }
#pragma unroll
    for (int i = 0; i < 8; i++) {
        int rel = j - i;
        dst[1 + i] = (rel == 0) ? B3 : (rel == 1) ? B2 : (rel == 2) ? B1
                   : (rel == 3) ? B0 : 0.0f;
    }
}

// ---------------------------------------------------------------------------
// fused pre-kernel: blocks [0,512) feat interior, [512,576) border,
// [576,3168) weight fold. 256 threads.
// ---------------------------------------------------------------------------
__global__ __launch_bounds__(256) void pre_kernel(
    const float* __restrict__ x, const float* __restrict__ bw,
    const float* __restrict__ sw, const float* __restrict__ ss) {
    extern __shared__ char dynsm[];
    const int blk = blockIdx.x;
    const int tid = threadIdx.x;

    if (blk < 512) {
        // ---- feat: blk = b*128 + iy*2 + xhalf ----
        float* slab   = reinterpret_cast<float*>(dynsm);            // 8448 B
        uint32_t* stH = reinterpret_cast<uint32_t*>(dynsm + 8448);  // 36992 B
        const int b  = blk >> 7;
        const int iy = (blk >> 1) & 63;
        const int xb = (blk & 1) * 32;

        for (int i = tid; i < 64 * 32; i += 256) {
            int c = i >> 5, px = i & 31;
            slab[c * 33 + px] = x[(((b * 64 + c) * 64 + iy) << 6) + xb + px];
        }
        __syncthreads();

        const int px = tid >> 3;
        const int cg = tid & 7;
#pragma unroll
        for (int pair = 0; pair < 4; pair++) {
            int c0 = cg * 8 + pair * 2;
            float f[18];
            feat9(slab[c0 * 33 + px], f);
            feat9(slab[(c0 + 1) * 33 + px], f + 9);
            int wb = px * 289 + cg * 36 + pair * 9;
#pragma unroll
            for (int q = 0; q < 9; q++) {
                __half2 th = __halves2half2(__float2half_rn(f[2 * q]),
                                            __float2half_rn(f[2 * q + 1]));
                stH[wb + q] = *reinterpret_cast<uint32_t*>(&th);
            }
        }
        __syncthreads();

        const size_t pixbase = ((size_t)((b * PH + iy + 1) * PW + xb + 1)) * CF;
        uint32_t* dH = reinterpret_cast<uint32_t*>(g_Ff + pixbase);
        for (int i = tid; i < 32 * 288; i += 256) {
            int p = i / 288, w = i - p * 288;
            dH[i] = stH[p * 289 + w];
        }
    } else if (blk < 576) {
        // ---- border: padded border pixels get features of x = 0 ----
        float zf[9];
        feat9(0.0f, zf);
        __half zh[9];
#pragma unroll
        for (int q = 0; q < 9; q++) zh[q] = __float2half_rn(zf[q]);

        for (int i = blk - 512; i < 4 * 260; i += 64) {
            int b = i / 260, r = i - b * 260;
            int py, pxx;
            if (r < 66)        { py = 0;  pxx = r; }
            else if (r < 132)  { py = 65; pxx = r - 66; }
            else { int t = r - 132; py = 1 + (t >> 1); pxx = (t & 1) * 65; }
            __half* dH = g_Ff + ((size_t)((b * PH + py) * PW + pxx)) * CF;
            for (int e = tid; e < CF; e += 256)
                dH[e] = zh[e % 9];
        }
    } else {
        // ---- weight fold -> [o][kk], kk = tap*576 + c*9 + ck, d = c*9+tap --
        int idx = (blk - 576) * 256 + tid;
        if (idx >= OUTC * KTOT) return;
        int o   = idx / KTOT;
        int kk  = idx - o * KTOT;
        int tap = kk / 576;
        int r   = kk - tap * 576;
        int c   = r / 9;
        int ck  = r - c * 9;
        int d   = c * 9 + tap;
        float v = ck ? sw[(o * 576 + d) * 8 + (ck - 1)] * ss[o * 576 + d]
                     : bw[o * 576 + d];
        g_Bf[idx] = __float2half_rn(v);
    }
}

// ---------------------------------------------------------------------------
// GEMM: 128 CTAs, M=128 x N=128, K=5184, fp16 mma.sync.
// 512 threads: 8 tiles of 64x32, warp pair (kg=0/1) K-splits each chunk.
// 6-stage pipeline, barrier per 128-K. Stage (32KB): [A 16K][B 16K].
// ---------------------------------------------------------------------------
#define STAGE_BYTES 32768
#define T_A 0
#define T_B 16384

__global__ __launch_bounds__(512, 1) void gemm_kernel(float* __restrict__ out) {
    extern __shared__ char dynsm[];
    uint32_t raw  = smem_u32(dynsm);
    uint32_t base = (raw + 1023u) & ~1023u;

    const int tid  = threadIdx.x;
    const int wid  = tid >> 5;
    const int lane = tid & 31;
    const int wm   = wid & 1;          // m half: 0,64
    const int wn   = (wid >> 1) & 3;   // n quarter: 0,32,64,96
    const int kg   = wid >> 3;         // K-split group 0/1
    const int mbase = blockIdx.x * 128;

    // ---- cp.async mapping: row = tid>>2 (0..127), seg = tid&3 (32B quarter)
    const int row = tid >> 2;
    const int seg = tid & 3;
    const int npix = mbase + row;
    const int pb = npix >> 12;
    const int oy = (npix >> 6) & 63;
    const int ox = npix & 63;
    const __half* ap = g_Ff + ((size_t)((pb * PH + oy) * PW + ox)) * CF;
    const __half* bp = g_Bf + (size_t)row * KTOT;
    const uint32_t rowterm = (uint32_t)row * 128;
    const uint32_t rowpat  = ((uint32_t)row & 7) << 4;

    auto load_chunk = [&](int kc, int stage) {
        int tap = kc / 9;
        int sub = kc - tap * 9;
        int kh = tap / 3, kw = tap - kh * 3;
        int aoff = (kh * PW + kw) * CF + sub * 64 + seg * 16;  // fp16 elements
        int boff = kc * 64 + seg * 16;
        const char* sA = (const char*)(ap + aoff);
        const char* sB = (const char*)(bp + boff);
        uint32_t sb = base + (uint32_t)stage * STAGE_BYTES + rowterm;
#pragma unroll
        for (int q = 0; q < 2; q++) {
            uint32_t kb = (uint32_t)(seg * 32 + q * 16);
            uint32_t d  = sb + (kb ^ rowpat);
            CP16(d + T_A, sA + q * 16);
            CP16(d + T_B, sB + q * 16);
        }
        CP_COMMIT();
    };

    // ---- ldmatrix lane addressing (64x32 warp tile) ----
    const int rA  = lane & 15;
    const uint32_t kA = ((uint32_t)(lane >> 4)) * 16;   // bytes
    uint32_t aRow[4], aPat[4];
#pragma unroll
    for (int mt = 0; mt < 4; mt++) {
        int rr = wm * 64 + mt * 16 + rA;
        aRow[mt] = (uint32_t)rr * 128;
        aPat[mt] = ((uint32_t)rr & 7) << 4;
    }
    const int rBl = (lane & 7) + ((lane >> 4) & 1) * 8;
    const uint32_t kB = ((uint32_t)((lane >> 3) & 1)) * 16;
    uint32_t bRow[2], bPat[2];
#pragma unroll
    for (int nt = 0; nt < 2; nt++) {
        int rr = wn * 32 + nt * 16 + rBl;
        bRow[nt] = (uint32_t)rr * 128;
        bPat[nt] = ((uint32_t)rr & 7) << 4;
    }

    float acc[4][4][4];
#pragma unroll
    for (int i = 0; i < 4; i++)
#pragma unroll
        for (int j = 0; j < 4; j++)
#pragma unroll
            for (int q = 0; q < 4; q++) acc[i][j][q] = 0.0f;

    uint32_t af[4][4], bf[2][4];

    // one 16-K slice: 4 A-LDSM4 + 2 B-LDSM4 then 16 MMAs
    auto do_slice = [&](uint32_t bb, int kk) {
        const uint32_t kbyte = (uint32_t)(kk * 32);
#pragma unroll
        for (int mt = 0; mt < 4; mt++) {
            uint32_t addr = bb + T_A + aRow[mt] + ((kbyte + kA) ^ aPat[mt]);
            LDSM4(af[mt][0], af[mt][1], af[mt][2], af[mt][3], addr);
        }
#pragma unroll
        for (int nt = 0; nt < 2; nt++) {
            uint32_t addr = bb + T_B + bRow[nt] + ((kbyte + kB) ^ bPat[nt]);
            LDSM4(bf[nt][0], bf[nt][1], bf[nt][2], bf[nt][3], addr);
        }
#pragma unroll
        for (int nt = 0; nt < 2; nt++)
#pragma unroll
            for (int mt = 0; mt < 4; mt++)
#pragma unroll
                for (int sub = 0; sub < 2; sub++)
                    MMA16816(acc[mt][nt * 2 + sub], af[mt],
                             bf[nt][sub * 2], bf[nt][sub * 2 + 1]);
    };

    const int kk0 = kg * 2;   // this warp's K slices within each chunk

    // prologue: chunks 0..3 into stages 0..3
#pragma unroll
    for (int s = 0; s < 4; s++) load_chunk(s, s);

    // mainloop: 40 iterations x 2 chunks; chunk c lives in stage c % 6
    int s0 = 0;
    for (int it = 0; it < 40; it++) {
        const int c0 = it * 2;
        CP_WAIT(2);
        __syncthreads();

        const int ls0 = (s0 >= 2) ? s0 - 2 : s0 + 4;   // (s0+4) mod 6
        load_chunk(c0 + 4, ls0);
        load_chunk(c0 + 5, (ls0 + 1 == 6) ? 0 : ls0 + 1);

        const uint32_t bbA = base + (uint32_t)s0 * STAGE_BYTES;
        const uint32_t bbB = bbA + STAGE_BYTES;
        do_slice(bbA, kk0);
        do_slice(bbA, kk0 + 1);
        do_slice(bbB, kk0);
        do_slice(bbB, kk0 + 1);

        s0 += 2; if (s0 == 6) s0 = 0;
    }
    // final chunk 80 (stage 80 % 6 == 2 == s0 here)
    CP_WAIT(0);
    __syncthreads();
    {
        const uint32_t bbA = base + (uint32_t)s0 * STAGE_BYTES;
        do_slice(bbA, kk0);
        do_slice(bbA, kk0 + 1);
    }
    __syncthreads();

    // ---- epilogue: K-split reduction through smem, then coalesced write ---
    float* st = reinterpret_cast<float*>(dynsm + (base - raw));
    const int g  = lane >> 2;
    const int tg = lane & 3;

    // phase 1: kg==1 warps store their partial sums
    if (kg == 1) {
#pragma unroll
        for (int mt = 0; mt < 4; mt++) {
#pragma unroll
            for (int n8 = 0; n8 < 4; n8++) {
                int m0 = wm * 64 + mt * 16 + g;
                int n0 = wn * 32 + n8 * 8 + tg * 2;
                const float* c = acc[mt][n8];
                st[m0 * 129 + n0]           = c[0];
                st[m0 * 129 + n0 + 1]       = c[1];
                st[(m0 + 8) * 129 + n0]     = c[2];
                st[(m0 + 8) * 129 + n0 + 1] = c[3];
            }
        }
    }
    __syncthreads();
    // phase 2: kg==0 warps add theirs
    if (kg == 0) {
#pragma unroll
        for (int mt = 0; mt < 4; mt++) {
#pragma unroll
            for (int n8 = 0; n8 < 4; n8++) {
                int m0 = wm * 64 + mt * 16 + g;
                int n0 = wn * 32 + n8 * 8 + tg * 2;
                const float* c = acc[mt][n8];
                st[m0 * 129 + n0]           += c[0];
                st[m0 * 129 + n0 + 1]       += c[1];
                st[(m0 + 8) * 129 + n0]     += c[2];
                st[(m0 + 8) * 129 + n0 + 1] += c[3];
            }
        }
    }
    __syncthreads();

    const int b_ = mbase >> 12;
    const int spb = mbase & 4095;
#pragma unroll
    for (int r = 0; r < 32; r++) {
        int idx = r * 512 + tid;
        int o = idx >> 7;
        int m = idx & 127;
        out[(((size_t)(b_ * OUTC + o)) << 12) + spb + m] = st[m * 129 + o];
    }
}

// ---------------------------------------------------------------------------
extern "C" void kernel_launch(void* const* d_in, const int* in_sizes, int n_in,
                              void* d_out, int out_size) {
    const float* x  = (const float*)d_in[0];
    const float* bw = (const float*)d_in[1];
    const float* sw = (const float*)d_in[2];
    const float* ss = (const float*)d_in[3];
    float* out = (float*)d_out;

    cudaFuncSetAttribute(pre_kernel, cudaFuncAttributeMaxDynamicSharedMemorySize, 50176);
    cudaFuncSetAttribute(gemm_kernel, cudaFuncAttributeMaxDynamicSharedMemorySize, 197632);

    // blocks: 512 feat + 64 border + ceil(663552/256)=2592 weight
    pre_kernel<<<512 + 64 + 2592, 256, 45440>>>(x, bw, sw, ss);
    gemm_kernel<<<128, 512, 197632>>>(out);
}